// round 2
// baseline (speedup 1.0000x reference)
#include <cuda_runtime.h>

// Problem constants
#define Bk  2048
#define Tk  100
#define Hk  256
#define Lk  128
#define NVk 5
#define Rk  8
#define OW  512   // H + 2L

__device__ __forceinline__ void fma8(float acc[Rk], float4 a0, float4 a1, float wv) {
    acc[0] = fmaf(a0.x, wv, acc[0]); acc[1] = fmaf(a0.y, wv, acc[1]);
    acc[2] = fmaf(a0.z, wv, acc[2]); acc[3] = fmaf(a0.w, wv, acc[3]);
    acc[4] = fmaf(a1.x, wv, acc[4]); acc[5] = fmaf(a1.y, wv, acc[5]);
    acc[6] = fmaf(a1.z, wv, acc[6]); acc[7] = fmaf(a1.w, wv, acc[7]);
}

__device__ __forceinline__ float sigmoidf_fast(float x) {
    return 1.0f / (1.0f + __expf(-x));
}

// One persistent block per 8 batch rows; runs the full T=100 scan privately.
// Thread j owns output column j. h kept in smem transposed [k][row] so the
// k-loop reads it as two broadcast LDS.128.
__global__ __launch_bounds__(256, 2)
void gru_decoder_kernel(
    const float* __restrict__ x_seq,   // [B,T,NV]
    const float* __restrict__ hidden,  // [B,H]
    const float* __restrict__ tree,    // [B,L]
    const float* __restrict__ graph,   // [B,L]
    const int*   __restrict__ lengths, // [B]
    const float* __restrict__ Wcs, const float* __restrict__ bcs, // [H+L,H],[H]
    const float* __restrict__ Wz,  const float* __restrict__ bz,  // [NV+H,H],[H]
    const float* __restrict__ Wr,  const float* __restrict__ br,
    const float* __restrict__ Wh,  const float* __restrict__ bh,
    float* __restrict__ out)
{
    __shared__ __align__(16) float hs[Hk][Rk];      // h_t, transposed [k][row]
    __shared__ __align__(16) float rh[Hk][Rk];      // r * h, transposed
    __shared__ __align__(16) float cv[Hk + Lk][Rk]; // prologue concat vec
    __shared__ float xs[Rk][8];                     // x_t per row (padded 5->8)
    __shared__ int   slen[Rk];

    const int j    = threadIdx.x;        // column 0..255
    const int row0 = blockIdx.x * Rk;

    float* out_newh = out;                          // [B,H]
    float* out_all  = out + Bk * Hk;                // [B,T,OW]
    float* out_seg  = out + Bk * Hk + Bk * Tk * OW; // [B,H]

    // Preload x-part weight columns (K=5 rows of each W) and latent values.
    float wzx[NVk], wrx[NVk], whx[NVk];
#pragma unroll
    for (int v = 0; v < NVk; v++) {
        wzx[v] = Wz[v * Hk + j];
        wrx[v] = Wr[v * Hk + j];
        whx[v] = Wh[v * Hk + j];
    }
    float lat[Rk];
#pragma unroll
    for (int r = 0; r < Rk; r++)
        lat[r] = (j < Lk) ? tree[(row0 + r) * Lk + j]
                          : graph[(row0 + r) * Lk + (j - Lk)];

    if (j < Rk) slen[j] = lengths[row0 + j];

    // Fill concat vec [hidden(256) ; graph(128)] transposed.
    for (int idx = j; idx < Rk * (Hk + Lk); idx += Hk) {
        int r = idx / (Hk + Lk);
        int k = idx % (Hk + Lk);
        cv[k][r] = (k < Hk) ? hidden[(row0 + r) * Hk + k]
                            : graph[(row0 + r) * Lk + (k - Hk)];
    }
    __syncthreads();

    // h0 = relu(cv @ Wcs + bcs)
    {
        float acc[Rk];
        const float b0 = bcs[j];
#pragma unroll
        for (int r = 0; r < Rk; r++) acc[r] = b0;
        const float* pcs = Wcs + j;
#pragma unroll 4
        for (int k = 0; k < Hk + Lk; k++) {
            float wv  = pcs[k * Hk];
            float4 a0 = *(const float4*)&cv[k][0];
            float4 a1 = *(const float4*)&cv[k][4];
            fma8(acc, a0, a1, wv);
        }
#pragma unroll
        for (int r = 0; r < Rk; r++) hs[j][r] = fmaxf(acc[r], 0.0f);
    }

    float seg[Rk];
#pragma unroll
    for (int r = 0; r < Rk; r++) seg[r] = -1e30f;

    const float bz_j = bz[j], br_j = br[j], bh_j = bh[j];
    const float* pz = Wz + NVk * Hk + j;
    const float* pr = Wr + NVk * Hk + j;
    const float* ph = Wh + NVk * Hk + j;

    // Rotate each block's k-sweep start to decorrelate LTS slice pressure
    // (all 256 blocks stream the same 768KB of weights per step).
    const int koff = (blockIdx.x * 53) & (Hk - 1);

    for (int t = 0; t < Tk; t++) {
        __syncthreads();  // hs/rh writes from previous step visible
        if (j < Rk * NVk)
            xs[j / NVk][j % NVk] =
                x_seq[(row0 + j / NVk) * (Tk * NVk) + t * NVk + (j % NVk)];
        __syncthreads();

        // ---- stage 1: z and r pre-activations ----
        float accz[Rk], accr[Rk];
#pragma unroll
        for (int r = 0; r < Rk; r++) {
            float az = bz_j, ar = br_j;
#pragma unroll
            for (int v = 0; v < NVk; v++) {
                az = fmaf(xs[r][v], wzx[v], az);
                ar = fmaf(xs[r][v], wrx[v], ar);
            }
            accz[r] = az; accr[r] = ar;
        }
#pragma unroll 4
        for (int k = koff; k < Hk; k++) {
            float wz = pz[k * Hk];
            float wr = pr[k * Hk];
            float4 a0 = *(const float4*)&hs[k][0];
            float4 a1 = *(const float4*)&hs[k][4];
            fma8(accz, a0, a1, wz);
            fma8(accr, a0, a1, wr);
        }
#pragma unroll 4
        for (int k = 0; k < koff; k++) {
            float wz = pz[k * Hk];
            float wr = pr[k * Hk];
            float4 a0 = *(const float4*)&hs[k][0];
            float4 a1 = *(const float4*)&hs[k][4];
            fma8(accz, a0, a1, wz);
            fma8(accr, a0, a1, wr);
        }

        float zv[Rk];
#pragma unroll
        for (int r = 0; r < Rk; r++) {
            zv[r]    = sigmoidf_fast(accz[r]);
            float rv = sigmoidf_fast(accr[r]);
            rh[j][r] = rv * hs[j][r];
        }
        __syncthreads();  // rh complete before stage 2 reads

        // ---- stage 2: candidate pre-activation ----
        float acch[Rk];
#pragma unroll
        for (int r = 0; r < Rk; r++) {
            float a = bh_j;
#pragma unroll
            for (int v = 0; v < NVk; v++) a = fmaf(xs[r][v], whx[v], a);
            acch[r] = a;
        }
#pragma unroll 4
        for (int k = koff; k < Hk; k++) {
            float wh = ph[k * Hk];
            float4 a0 = *(const float4*)&rh[k][0];
            float4 a1 = *(const float4*)&rh[k][4];
            fma8(acch, a0, a1, wh);
        }
#pragma unroll 4
        for (int k = 0; k < koff; k++) {
            float wh = ph[k * Hk];
            float4 a0 = *(const float4*)&rh[k][0];
            float4 a1 = *(const float4*)&rh[k][4];
            fma8(acch, a0, a1, wh);
        }

        // ---- combine + epilogue (own-column smem only; no hazard) ----
#pragma unroll
        for (int r = 0; r < Rk; r++) {
            float pre  = tanhf(acch[r]);
            float hold = hs[j][r];
            float hn   = (1.0f - zv[r]) * hold + zv[r] * pre;
            int   len  = slen[r];
            bool  valid = (t < len);

            int base = (row0 + r) * (Tk * OW) + t * OW;
            out_all[base + j]      = valid ? hn : 0.0f;
            out_all[base + Hk + j] = valid ? lat[r] : 0.0f;

            if (valid) seg[r] = fmaxf(seg[r], hn);
            if (t == len - 1) out_newh[(row0 + r) * Hk + j] = hn;

            hs[j][r] = hn;  // own element; all cross-thread hs reads done pre mid-sync
        }
    }

#pragma unroll
    for (int r = 0; r < Rk; r++)
        out_seg[(row0 + r) * Hk + j] = seg[r];
}

extern "C" void kernel_launch(void* const* d_in, const int* in_sizes, int n_in,
                              void* d_out, int out_size) {
    const float* x_seq   = (const float*)d_in[0];
    const float* hidden  = (const float*)d_in[1];
    const float* tree    = (const float*)d_in[2];
    const float* graph   = (const float*)d_in[3];
    const int*   lengths = (const int*)  d_in[4];
    const float* Wcs = (const float*)d_in[5];
    const float* bcs = (const float*)d_in[6];
    const float* Wz  = (const float*)d_in[7];
    const float* bz  = (const float*)d_in[8];
    const float* Wr  = (const float*)d_in[9];
    const float* br  = (const float*)d_in[10];
    const float* Wh  = (const float*)d_in[11];
    const float* bh  = (const float*)d_in[12];
    float* out = (float*)d_out;

    gru_decoder_kernel<<<Bk / Rk, Hk>>>(
        x_seq, hidden, tree, graph, lengths,
        Wcs, bcs, Wz, bz, Wr, br, Wh, bh, out);
}

// round 3
// speedup vs baseline: 1.0455x; 1.0455x over previous
#include <cuda_runtime.h>

// Problem constants
#define Bk  2048
#define Tk  100
#define Hk  256
#define Lk  128
#define NVk 5
#define Rk  8
#define OW  512   // H + 2L

// Repacked weights (one-time per launch; __device__ scratch is allowed).
// g_wzr[k*Hk + j] = ((wz,wz),(wr,wr))  -- LDG.128 feeds FFMA2 directly
// g_whh[k*Hk + j] = (wh,wh)            -- LDG.64
__device__ __align__(16) ulonglong2        g_wzr[Hk * Hk];
__device__ __align__(8)  unsigned long long g_whh[Hk * Hk];

__device__ __forceinline__ void fma2(unsigned long long& d,
                                     unsigned long long a,
                                     unsigned long long b) {
    asm("fma.rn.f32x2 %0, %1, %2, %0;" : "+l"(d) : "l"(a), "l"(b));
}
__device__ __forceinline__ unsigned long long pack2(float lo, float hi) {
    unsigned long long r;
    asm("mov.b64 %0, {%1, %2};" : "=l"(r) : "f"(lo), "f"(hi));
    return r;
}
__device__ __forceinline__ float2 unpack2(unsigned long long p) {
    float2 f;
    asm("mov.b64 {%0, %1}, %2;" : "=f"(f.x), "=f"(f.y) : "l"(p));
    return f;
}
__device__ __forceinline__ float sigmoidf_fast(float x) {
    return 1.0f / (1.0f + __expf(-x));
}
__device__ __forceinline__ void fma8s(float acc[Rk], float4 a0, float4 a1, float wv) {
    acc[0] = fmaf(a0.x, wv, acc[0]); acc[1] = fmaf(a0.y, wv, acc[1]);
    acc[2] = fmaf(a0.z, wv, acc[2]); acc[3] = fmaf(a0.w, wv, acc[3]);
    acc[4] = fmaf(a1.x, wv, acc[4]); acc[5] = fmaf(a1.y, wv, acc[5]);
    acc[6] = fmaf(a1.z, wv, acc[6]); acc[7] = fmaf(a1.w, wv, acc[7]);
}

// One-time repack of the hidden-part GRU weights.
__global__ void repack_kernel(const float* __restrict__ Wz,
                              const float* __restrict__ Wr,
                              const float* __restrict__ Wh) {
    int idx = blockIdx.x * blockDim.x + threadIdx.x;  // 65536 over [k][j]
    int k = idx >> 8, j = idx & (Hk - 1);
    float wz = Wz[(NVk + k) * Hk + j];
    float wr = Wr[(NVk + k) * Hk + j];
    float wh = Wh[(NVk + k) * Hk + j];
    g_wzr[idx] = make_ulonglong2(pack2(wz, wz), pack2(wr, wr));
    g_whh[idx] = pack2(wh, wh);
}

// One persistent block per 8 batch rows; full T=100 scan in-block.
// Thread j owns column j; h kept in smem transposed [k][row].
__global__ __launch_bounds__(256, 2)
void gru_decoder_kernel(
    const float* __restrict__ x_seq,   // [B,T,NV]
    const float* __restrict__ hidden,  // [B,H]
    const float* __restrict__ tree,    // [B,L]
    const float* __restrict__ graph,   // [B,L]
    const int*   __restrict__ lengths, // [B]
    const float* __restrict__ Wcs, const float* __restrict__ bcs,
    const float* __restrict__ Wz,  const float* __restrict__ bz,
    const float* __restrict__ Wr,  const float* __restrict__ br,
    const float* __restrict__ Wh,  const float* __restrict__ bh,
    float* __restrict__ out)
{
    __shared__ __align__(16) float hs[Hk][Rk];      // h_t transposed
    __shared__ __align__(16) float rh[Hk][Rk];      // r*h transposed
    __shared__ __align__(16) float cv[Hk + Lk][Rk]; // prologue concat
    __shared__ float xs[Rk][8];
    __shared__ int   slen[Rk];

    const int j    = threadIdx.x;
    const int row0 = blockIdx.x * Rk;

    float* out_newh = out;
    float* out_all  = out + Bk * Hk;
    float* out_seg  = out + Bk * Hk + Bk * Tk * OW;

    // x-part weight columns + latents
    float wzx[NVk], wrx[NVk], whx[NVk];
#pragma unroll
    for (int v = 0; v < NVk; v++) {
        wzx[v] = Wz[v * Hk + j];
        wrx[v] = Wr[v * Hk + j];
        whx[v] = Wh[v * Hk + j];
    }
    float lat[Rk];
#pragma unroll
    for (int r = 0; r < Rk; r++)
        lat[r] = (j < Lk) ? tree[(row0 + r) * Lk + j]
                          : graph[(row0 + r) * Lk + (j - Lk)];
    if (j < Rk) slen[j] = lengths[row0 + j];

    for (int idx = j; idx < Rk * (Hk + Lk); idx += Hk) {
        int r = idx / (Hk + Lk);
        int k = idx % (Hk + Lk);
        cv[k][r] = (k < Hk) ? hidden[(row0 + r) * Hk + k]
                            : graph[(row0 + r) * Lk + (k - Hk)];
    }
    __syncthreads();

    // h0 = relu(cv @ Wcs + bcs)   (one-time; scalar path fine)
    {
        float acc[Rk];
        const float b0 = bcs[j];
#pragma unroll
        for (int r = 0; r < Rk; r++) acc[r] = b0;
        const float* pcs = Wcs + j;
#pragma unroll 4
        for (int k = 0; k < Hk + Lk; k++) {
            float wv  = pcs[k * Hk];
            float4 a0 = *(const float4*)&cv[k][0];
            float4 a1 = *(const float4*)&cv[k][4];
            fma8s(acc, a0, a1, wv);
        }
#pragma unroll
        for (int r = 0; r < Rk; r++) hs[j][r] = fmaxf(acc[r], 0.0f);
    }

    float seg[Rk];
#pragma unroll
    for (int r = 0; r < Rk; r++) seg[r] = -1e30f;

    const float bz_j = bz[j], br_j = br[j], bh_j = bh[j];
    const ulonglong2*        pzr = g_wzr + j;
    const unsigned long long* phh = g_whh + j;

    // Rotate k-sweep start per block (octet-aligned so unroll-8 stays contiguous).
    const int koff = (blockIdx.x & 31) << 3;

    for (int t = 0; t < Tk; t++) {
        __syncthreads();
        if (j < Rk * NVk)
            xs[j / NVk][j % NVk] =
                x_seq[(row0 + j / NVk) * (Tk * NVk) + t * NVk + (j % NVk)];
        __syncthreads();

        // ---- stage 1: z & r pre-activations (packed f32x2) ----
        unsigned long long accz[4], accr[4];
        {
            float az[Rk], ar[Rk];
#pragma unroll
            for (int r = 0; r < Rk; r++) {
                float a = bz_j, b = br_j;
#pragma unroll
                for (int v = 0; v < NVk; v++) {
                    a = fmaf(xs[r][v], wzx[v], a);
                    b = fmaf(xs[r][v], wrx[v], b);
                }
                az[r] = a; ar[r] = b;
            }
#pragma unroll
            for (int p = 0; p < 4; p++) {
                accz[p] = pack2(az[2 * p], az[2 * p + 1]);
                accr[p] = pack2(ar[2 * p], ar[2 * p + 1]);
            }
        }
#pragma unroll 8
        for (int kk = 0; kk < Hk; kk++) {
            int k = (kk + koff) & (Hk - 1);
            ulonglong2 w  = pzr[k * Hk];           // (wz,wz),(wr,wr)
            ulonglong2 ha = *(const ulonglong2*)&hs[k][0];
            ulonglong2 hb = *(const ulonglong2*)&hs[k][4];
            fma2(accz[0], ha.x, w.x); fma2(accz[1], ha.y, w.x);
            fma2(accz[2], hb.x, w.x); fma2(accz[3], hb.y, w.x);
            fma2(accr[0], ha.x, w.y); fma2(accr[1], ha.y, w.y);
            fma2(accr[2], hb.x, w.y); fma2(accr[3], hb.y, w.y);
        }

        float zv[Rk];
#pragma unroll
        for (int p = 0; p < 4; p++) {
            float2 z2 = unpack2(accz[p]);
            float2 r2 = unpack2(accr[p]);
            zv[2 * p]     = sigmoidf_fast(z2.x);
            zv[2 * p + 1] = sigmoidf_fast(z2.y);
            rh[j][2 * p]     = sigmoidf_fast(r2.x) * hs[j][2 * p];
            rh[j][2 * p + 1] = sigmoidf_fast(r2.y) * hs[j][2 * p + 1];
        }
        __syncthreads();

        // ---- stage 2: candidate pre-activation ----
        unsigned long long acch[4];
        {
            float ah[Rk];
#pragma unroll
            for (int r = 0; r < Rk; r++) {
                float a = bh_j;
#pragma unroll
                for (int v = 0; v < NVk; v++) a = fmaf(xs[r][v], whx[v], a);
                ah[r] = a;
            }
#pragma unroll
            for (int p = 0; p < 4; p++) acch[p] = pack2(ah[2 * p], ah[2 * p + 1]);
        }
#pragma unroll 8
        for (int kk = 0; kk < Hk; kk++) {
            int k = (kk + koff) & (Hk - 1);
            unsigned long long wh = phh[k * Hk];   // (wh,wh)
            ulonglong2 ra = *(const ulonglong2*)&rh[k][0];
            ulonglong2 rb = *(const ulonglong2*)&rh[k][4];
            fma2(acch[0], ra.x, wh); fma2(acch[1], ra.y, wh);
            fma2(acch[2], rb.x, wh); fma2(acch[3], rb.y, wh);
        }

        // ---- combine + epilogue ----
#pragma unroll
        for (int p = 0; p < 4; p++) {
            float2 h2 = unpack2(acch[p]);
#pragma unroll
            for (int q = 0; q < 2; q++) {
                int   r    = 2 * p + q;
                float pre  = tanhf(q ? h2.y : h2.x);
                float hold = hs[j][r];
                float hn   = (1.0f - zv[r]) * hold + zv[r] * pre;
                int   len  = slen[r];
                bool  valid = (t < len);

                int base = (row0 + r) * (Tk * OW) + t * OW;
                out_all[base + j]      = valid ? hn : 0.0f;
                out_all[base + Hk + j] = valid ? lat[r] : 0.0f;

                if (valid) seg[r] = fmaxf(seg[r], hn);
                if (t == len - 1) out_newh[(row0 + r) * Hk + j] = hn;

                hs[j][r] = hn;
            }
        }
    }

#pragma unroll
    for (int r = 0; r < Rk; r++)
        out_seg[(row0 + r) * Hk + j] = seg[r];
}

extern "C" void kernel_launch(void* const* d_in, const int* in_sizes, int n_in,
                              void* d_out, int out_size) {
    const float* x_seq   = (const float*)d_in[0];
    const float* hidden  = (const float*)d_in[1];
    const float* tree    = (const float*)d_in[2];
    const float* graph   = (const float*)d_in[3];
    const int*   lengths = (const int*)  d_in[4];
    const float* Wcs = (const float*)d_in[5];
    const float* bcs = (const float*)d_in[6];
    const float* Wz  = (const float*)d_in[7];
    const float* bz  = (const float*)d_in[8];
    const float* Wr  = (const float*)d_in[9];
    const float* br  = (const float*)d_in[10];
    const float* Wh  = (const float*)d_in[11];
    const float* bh  = (const float*)d_in[12];
    float* out = (float*)d_out;

    repack_kernel<<<Hk * Hk / 256, 256>>>(Wz, Wr, Wh);
    gru_decoder_kernel<<<Bk / Rk, Hk>>>(
        x_seq, hidden, tree, graph, lengths,
        Wcs, bcs, Wz, bz, Wr, br, Wh, bh, out);
}

// round 4
// speedup vs baseline: 1.2993x; 1.2428x over previous
#include <cuda_runtime.h>

// Problem constants
#define Bk  2048
#define Tk  100
#define Hk  256
#define Lk  128
#define NVk 5
#define Rk  16      // batch rows per block (two 8-row halves)
#define RH  8       // rows per thread
#define OW  512     // H + 2L

// Repacked stage-1 weights: g_wzr[k*Hk + j] = (wz, wr)  (8B, coalesced LDG.64)
__device__ __align__(8) float2 g_wzr[Hk * Hk];

__device__ __forceinline__ void fma2(unsigned long long& d,
                                     unsigned long long a,
                                     unsigned long long b) {
    asm("fma.rn.f32x2 %0, %1, %2, %0;" : "+l"(d) : "l"(a), "l"(b));
}
__device__ __forceinline__ unsigned long long pack2(float lo, float hi) {
    unsigned long long r;
    asm("mov.b64 %0, {%1, %2};" : "=l"(r) : "f"(lo), "f"(hi));
    return r;
}
__device__ __forceinline__ float2 unpack2(unsigned long long p) {
    float2 f;
    asm("mov.b64 {%0, %1}, %2;" : "=f"(f.x), "=f"(f.y) : "l"(p));
    return f;
}
__device__ __forceinline__ float sigmoidf_fast(float x) {
    return 1.0f / (1.0f + __expf(-x));
}
__device__ __forceinline__ void fma8s(float acc[RH], float4 a0, float4 a1, float wv) {
    acc[0] = fmaf(a0.x, wv, acc[0]); acc[1] = fmaf(a0.y, wv, acc[1]);
    acc[2] = fmaf(a0.z, wv, acc[2]); acc[3] = fmaf(a0.w, wv, acc[3]);
    acc[4] = fmaf(a1.x, wv, acc[4]); acc[5] = fmaf(a1.y, wv, acc[5]);
    acc[6] = fmaf(a1.z, wv, acc[6]); acc[7] = fmaf(a1.w, wv, acc[7]);
}

__global__ void repack_kernel(const float* __restrict__ Wz,
                              const float* __restrict__ Wr) {
    int idx = blockIdx.x * blockDim.x + threadIdx.x;  // 65536 over [k][j]
    int k = idx >> 8, j = idx & (Hk - 1);
    g_wzr[idx] = make_float2(Wz[(NVk + k) * Hk + j], Wr[(NVk + k) * Hk + j]);
}

// 128 persistent blocks x 512 threads. Block owns 16 batch rows; thread
// (j = tid&255, half = tid>>8) owns column j for rows [half*8, half*8+8).
// Both halves stream the same weights -> second half hits L1.
__global__ __launch_bounds__(512, 1)
void gru_decoder_kernel(
    const float* __restrict__ x_seq,   // [B,T,NV]
    const float* __restrict__ hidden,  // [B,H]
    const float* __restrict__ tree,    // [B,L]
    const float* __restrict__ graph,   // [B,L]
    const int*   __restrict__ lengths, // [B]
    const float* __restrict__ Wcs, const float* __restrict__ bcs,
    const float* __restrict__ Wz,  const float* __restrict__ bz,
    const float* __restrict__ Wr,  const float* __restrict__ br,
    const float* __restrict__ Wh,  const float* __restrict__ bh,
    float* __restrict__ out)
{
    __shared__ __align__(16) float hs[Hk][Rk];      // h_t transposed [k][row]
    __shared__ __align__(16) float rh[Hk][Rk];      // r*h transposed
    __shared__ __align__(16) float cv[Hk + Lk][Rk]; // prologue concat
    __shared__ float xs[Rk][8];
    __shared__ int   slen[Rk];

    const int tid   = threadIdx.x;
    const int j     = tid & (Hk - 1);
    const int rbase = (tid >> 8) << 3;   // 0 or 8
    const int row0  = blockIdx.x * Rk;

    float* out_newh = out;
    float* out_all  = out + Bk * Hk;
    float* out_seg  = out + Bk * Hk + Bk * Tk * OW;

    // x-part weight columns + latents for this thread's 8 rows
    float wzx[NVk], wrx[NVk], whx[NVk];
#pragma unroll
    for (int v = 0; v < NVk; v++) {
        wzx[v] = Wz[v * Hk + j];
        wrx[v] = Wr[v * Hk + j];
        whx[v] = Wh[v * Hk + j];
    }
    float lat[RH];
#pragma unroll
    for (int r = 0; r < RH; r++)
        lat[r] = (j < Lk) ? tree[(row0 + rbase + r) * Lk + j]
                          : graph[(row0 + rbase + r) * Lk + (j - Lk)];
    if (tid < Rk) slen[tid] = lengths[row0 + tid];

    for (int idx = tid; idx < Rk * (Hk + Lk); idx += 512) {
        int r = idx / (Hk + Lk);
        int k = idx % (Hk + Lk);
        cv[k][r] = (k < Hk) ? hidden[(row0 + r) * Hk + k]
                            : graph[(row0 + r) * Lk + (k - Hk)];
    }
    __syncthreads();

    // h0 = relu(cv @ Wcs + bcs)
    {
        float acc[RH];
        const float b0 = bcs[j];
#pragma unroll
        for (int r = 0; r < RH; r++) acc[r] = b0;
        const float* pcs = Wcs + j;
#pragma unroll 4
        for (int k = 0; k < Hk + Lk; k++) {
            float wv  = pcs[k * Hk];
            float4 a0 = *(const float4*)&cv[k][rbase];
            float4 a1 = *(const float4*)&cv[k][rbase + 4];
            fma8s(acc, a0, a1, wv);
        }
#pragma unroll
        for (int r = 0; r < RH; r++) hs[j][rbase + r] = fmaxf(acc[r], 0.0f);
    }

    float seg[RH];
#pragma unroll
    for (int r = 0; r < RH; r++) seg[r] = -1e30f;

    const float bz_j = bz[j], br_j = br[j], bh_j = bh[j];
    const float2* pzr = g_wzr + j;
    const float*  ph  = Wh + NVk * Hk + j;

    for (int t = 0; t < Tk; t++) {
        __syncthreads();
        if (tid < Rk * NVk)
            xs[tid / NVk][tid % NVk] =
                x_seq[(row0 + tid / NVk) * (Tk * NVk) + t * NVk + (tid % NVk)];
        __syncthreads();

        // ---- stage 1: z & r pre-activations (packed f32x2) ----
        unsigned long long accz[4], accr[4];
        {
            float az[RH], ar[RH];
#pragma unroll
            for (int r = 0; r < RH; r++) {
                float a = bz_j, b = br_j;
#pragma unroll
                for (int v = 0; v < NVk; v++) {
                    a = fmaf(xs[rbase + r][v], wzx[v], a);
                    b = fmaf(xs[rbase + r][v], wrx[v], b);
                }
                az[r] = a; ar[r] = b;
            }
#pragma unroll
            for (int p = 0; p < 4; p++) {
                accz[p] = pack2(az[2 * p], az[2 * p + 1]);
                accr[p] = pack2(ar[2 * p], ar[2 * p + 1]);
            }
        }
#pragma unroll 8
        for (int k = 0; k < Hk; k++) {
            float2 w = pzr[k * Hk];                     // (wz, wr)
            unsigned long long wzz = pack2(w.x, w.x);
            unsigned long long wrr = pack2(w.y, w.y);
            ulonglong2 ha = *(const ulonglong2*)&hs[k][rbase];
            ulonglong2 hb = *(const ulonglong2*)&hs[k][rbase + 4];
            fma2(accz[0], ha.x, wzz); fma2(accz[1], ha.y, wzz);
            fma2(accz[2], hb.x, wzz); fma2(accz[3], hb.y, wzz);
            fma2(accr[0], ha.x, wrr); fma2(accr[1], ha.y, wrr);
            fma2(accr[2], hb.x, wrr); fma2(accr[3], hb.y, wrr);
        }

        float zv[RH];
#pragma unroll
        for (int p = 0; p < 4; p++) {
            float2 z2 = unpack2(accz[p]);
            float2 r2 = unpack2(accr[p]);
            zv[2 * p]     = sigmoidf_fast(z2.x);
            zv[2 * p + 1] = sigmoidf_fast(z2.y);
            rh[j][rbase + 2 * p]     = sigmoidf_fast(r2.x) * hs[j][rbase + 2 * p];
            rh[j][rbase + 2 * p + 1] = sigmoidf_fast(r2.y) * hs[j][rbase + 2 * p + 1];
        }
        __syncthreads();

        // ---- stage 2: candidate pre-activation ----
        unsigned long long acch[4];
        {
            float ah[RH];
#pragma unroll
            for (int r = 0; r < RH; r++) {
                float a = bh_j;
#pragma unroll
                for (int v = 0; v < NVk; v++) a = fmaf(xs[rbase + r][v], whx[v], a);
                ah[r] = a;
            }
#pragma unroll
            for (int p = 0; p < 4; p++) acch[p] = pack2(ah[2 * p], ah[2 * p + 1]);
        }
#pragma unroll 8
        for (int k = 0; k < Hk; k++) {
            float whs = ph[k * Hk];                     // LDG.32
            unsigned long long whh = pack2(whs, whs);
            ulonglong2 ra = *(const ulonglong2*)&rh[k][rbase];
            ulonglong2 rb = *(const ulonglong2*)&rh[k][rbase + 4];
            fma2(acch[0], ra.x, whh); fma2(acch[1], ra.y, whh);
            fma2(acch[2], rb.x, whh); fma2(acch[3], rb.y, whh);
        }

        // ---- combine + epilogue ----
#pragma unroll
        for (int p = 0; p < 4; p++) {
            float2 h2 = unpack2(acch[p]);
#pragma unroll
            for (int q = 0; q < 2; q++) {
                int   r    = 2 * p + q;
                float pre  = tanhf(q ? h2.y : h2.x);
                float hold = hs[j][rbase + r];
                float hn   = (1.0f - zv[r]) * hold + zv[r] * pre;
                int   len  = slen[rbase + r];
                bool  valid = (t < len);

                int base = (row0 + rbase + r) * (Tk * OW) + t * OW;
                out_all[base + j]      = valid ? hn : 0.0f;
                out_all[base + Hk + j] = valid ? lat[r] : 0.0f;

                if (valid) seg[r] = fmaxf(seg[r], hn);
                if (t == len - 1) out_newh[(row0 + rbase + r) * Hk + j] = hn;

                hs[j][rbase + r] = hn;
            }
        }
    }

#pragma unroll
    for (int r = 0; r < RH; r++)
        out_seg[(row0 + rbase + r) * Hk + j] = seg[r];
}

extern "C" void kernel_launch(void* const* d_in, const int* in_sizes, int n_in,
                              void* d_out, int out_size) {
    const float* x_seq   = (const float*)d_in[0];
    const float* hidden  = (const float*)d_in[1];
    const float* tree    = (const float*)d_in[2];
    const float* graph   = (const float*)d_in[3];
    const int*   lengths = (const int*)  d_in[4];
    const float* Wcs = (const float*)d_in[5];
    const float* bcs = (const float*)d_in[6];
    const float* Wz  = (const float*)d_in[7];
    const float* bz  = (const float*)d_in[8];
    const float* Wr  = (const float*)d_in[9];
    const float* br  = (const float*)d_in[10];
    const float* Wh  = (const float*)d_in[11];
    const float* bh  = (const float*)d_in[12];
    float* out = (float*)d_out;

    repack_kernel<<<Hk * Hk / 256, 256>>>(Wz, Wr);
    gru_decoder_kernel<<<Bk / Rk, 512>>>(
        x_seq, hidden, tree, graph, lengths,
        Wcs, bcs, Wz, bz, Wr, br, Wh, bh, out);
}

// round 5
// speedup vs baseline: 1.3866x; 1.0672x over previous
#include <cuda_runtime.h>

// Problem constants
#define Bk  2048
#define Tk  100
#define Hk  256
#define Lk  128
#define NVk 5
#define Rk  16      // batch rows per block
#define OW  512     // H + 2L

#define HSTR 20     // smem row stride (floats) for hs/rh: 16 rows + pad, 80B (16B-aligned)
#define PEXSTR 18   // pexu stride in ull per j (144B, 16B-aligned)

// Dynamic smem layout (floats)
#define HS_OFF  0
#define RH_OFF  (Hk * HSTR)                // 5120
#define PEX_OFF (2 * Hk * HSTR)            // 10240 ; pexu = (ull*) here, Hk*PEXSTR ull
#define SMEM_F  (2 * Hk * HSTR + Hk * PEXSTR * 2)   // 19456 floats = 77824 B

typedef unsigned long long ull;

// Repacked stage-1 weights: g_wzr[k*Hk + j] = (wz, wr)
__device__ __align__(8) float2 g_wzr[Hk * Hk];

__device__ __forceinline__ void fma2(ull& d, ull a, ull b) {
    asm("fma.rn.f32x2 %0, %1, %2, %0;" : "+l"(d) : "l"(a), "l"(b));
}
__device__ __forceinline__ void add2(ull& d, ull a) {
    asm("add.rn.f32x2 %0, %0, %1;" : "+l"(d) : "l"(a));
}
__device__ __forceinline__ ull pack2(float lo, float hi) {
    ull r; asm("mov.b64 %0, {%1, %2};" : "=l"(r) : "f"(lo), "f"(hi)); return r;
}
__device__ __forceinline__ float2 unpack2(ull p) {
    float2 f; asm("mov.b64 {%0, %1}, %2;" : "=f"(f.x), "=f"(f.y) : "l"(p)); return f;
}
__device__ __forceinline__ float sigmoidf_fast(float x) {
    return 1.0f / (1.0f + __expf(-x));
}
__device__ __forceinline__ void fma8s(float acc[8], float4 a0, float4 a1, float wv) {
    acc[0] = fmaf(a0.x, wv, acc[0]); acc[1] = fmaf(a0.y, wv, acc[1]);
    acc[2] = fmaf(a0.z, wv, acc[2]); acc[3] = fmaf(a0.w, wv, acc[3]);
    acc[4] = fmaf(a1.x, wv, acc[4]); acc[5] = fmaf(a1.y, wv, acc[5]);
    acc[6] = fmaf(a1.z, wv, acc[6]); acc[7] = fmaf(a1.w, wv, acc[7]);
}

__global__ void repack_kernel(const float* __restrict__ Wz,
                              const float* __restrict__ Wr) {
    int idx = blockIdx.x * blockDim.x + threadIdx.x;
    int k = idx >> 8, j = idx & (Hk - 1);
    g_wzr[idx] = make_float2(Wz[(NVk + k) * Hk + j], Wr[(NVk + k) * Hk + j]);
}

// 128 blocks x 512 threads; block = 16 rows. Thread (j = tid&255, kh = tid>>8)
// accumulates ALL 16 rows over k-half [kh*128, kh*128+128): weights read once
// per block per step. Partial sums cross-exchanged via smem; thread (j,kh)
// finalizes rows kh*8..kh*8+8.
__global__ __launch_bounds__(512, 1)
void gru_decoder_kernel(
    const float* __restrict__ x_seq,   // [B,T,NV]
    const float* __restrict__ hidden,  // [B,H]
    const float* __restrict__ tree,    // [B,L]
    const float* __restrict__ graph,   // [B,L]
    const int*   __restrict__ lengths, // [B]
    const float* __restrict__ Wcs, const float* __restrict__ bcs,
    const float* __restrict__ Wz,  const float* __restrict__ bz,
    const float* __restrict__ Wr,  const float* __restrict__ br,
    const float* __restrict__ Wh,  const float* __restrict__ bh,
    float* __restrict__ out)
{
    extern __shared__ __align__(16) float smf[];
    float* hsb  = smf + HS_OFF;    // hs[k*HSTR + r]
    float* rhb  = smf + RH_OFF;    // rh[k*HSTR + r]
    ull*   pexu = (ull*)(smf + PEX_OFF);   // pexu[j*PEXSTR + slot]
    float* cvb  = smf + PEX_OFF;   // prologue overlay: cv[k*16 + r], k<384

    __shared__ float xs[Rk][8];
    __shared__ int   slen[Rk];

    const int tid  = threadIdx.x;
    const int j    = tid & (Hk - 1);
    const int kh   = tid >> 8;           // 0 or 1 (warp-uniform)
    const int k0   = kh << 7;            // own k-range start
    const int orow = kh << 3;            // own (finalized) rows start
    const int op0  = kh << 2;            // own pair start
    const int ep0  = 4 - op0;            // export pair start
    const int row0 = blockIdx.x * Rk;

    float* out_newh = out;
    float* out_all  = out + Bk * Hk;
    float* out_seg  = out + Bk * Hk + Bk * Tk * OW;

    // x-part weight columns + latents for own 8 rows
    float wzx[NVk], wrx[NVk], whx[NVk];
#pragma unroll
    for (int v = 0; v < NVk; v++) {
        wzx[v] = Wz[v * Hk + j];
        wrx[v] = Wr[v * Hk + j];
        whx[v] = Wh[v * Hk + j];
    }
    float lat[8];
#pragma unroll
    for (int r = 0; r < 8; r++)
        lat[r] = (j < Lk) ? tree[(row0 + orow + r) * Lk + j]
                          : graph[(row0 + orow + r) * Lk + (j - Lk)];
    if (tid < Rk) slen[tid] = lengths[row0 + tid];

    // Prologue: cv[k][r] (overlaid on pex region)
    for (int idx = tid; idx < Rk * (Hk + Lk); idx += 512) {
        int r = idx >> 9;          // 0..15  (wrong if not careful) -- compute properly:
        r = idx / (Hk + Lk);
        int k = idx - r * (Hk + Lk);
        cvb[k * 16 + r] = (k < Hk) ? hidden[(row0 + r) * Hk + k]
                                   : graph[(row0 + r) * Lk + (k - Hk)];
    }
    __syncthreads();

    // h0 = relu(cv @ Wcs + bcs) for own 8 rows
    {
        float acc[8];
        const float b0 = bcs[j];
#pragma unroll
        for (int r = 0; r < 8; r++) acc[r] = b0;
        const float* pcs = Wcs + j;
#pragma unroll 4
        for (int k = 0; k < Hk + Lk; k++) {
            float wv  = pcs[k * Hk];
            float4 a0 = *(const float4*)&cvb[k * 16 + orow];
            float4 a1 = *(const float4*)&cvb[k * 16 + orow + 4];
            fma8s(acc, a0, a1, wv);
        }
#pragma unroll
        for (int r = 0; r < 8; r++) hsb[j * HSTR + orow + r] = fmaxf(acc[r], 0.0f);
    }

    float seg[8];
#pragma unroll
    for (int r = 0; r < 8; r++) seg[r] = -1e30f;

    const float bz_j = bz[j], br_j = br[j], bh_j = bh[j];
    const float2* pzr = g_wzr + j;
    const float*  ph  = Wh + NVk * Hk + j;

    for (int t = 0; t < Tk; t++) {
        __syncthreads();   // hs stores + pex reads from prev step complete
        if (tid < Rk * NVk)
            xs[tid / NVk][tid % NVk] =
                x_seq[(row0 + tid / NVk) * (Tk * NVk) + t * NVk + (tid % NVk)];
        __syncthreads();

        // ---- stage 1: z,r partials for 16 rows over own k-half ----
        ull az[8], ar[8];
#pragma unroll
        for (int p = 0; p < 8; p++) {
            bool exp_p = (p >= ep0) && (p < ep0 + 4);
            if (exp_p) {   // bias + x-part folded into exported half only
                float z0 = bz_j, z1 = bz_j, r0 = br_j, r1 = br_j;
#pragma unroll
                for (int v = 0; v < NVk; v++) {
                    float x0 = xs[2 * p][v], x1 = xs[2 * p + 1][v];
                    z0 = fmaf(x0, wzx[v], z0); z1 = fmaf(x1, wzx[v], z1);
                    r0 = fmaf(x0, wrx[v], r0); r1 = fmaf(x1, wrx[v], r1);
                }
                az[p] = pack2(z0, z1); ar[p] = pack2(r0, r1);
            } else { az[p] = 0ULL; ar[p] = 0ULL; }
        }
#pragma unroll 4
        for (int kk = 0; kk < 128; kk++) {
            int k = k0 + kk;
            float2 w = pzr[k * Hk];
            ull wzz = pack2(w.x, w.x), wrr = pack2(w.y, w.y);
            const ulonglong2* hp = (const ulonglong2*)(hsb + k * HSTR);
            ulonglong2 hA = hp[0], hB = hp[1], hC = hp[2], hD = hp[3];
            fma2(az[0], hA.x, wzz); fma2(az[1], hA.y, wzz);
            fma2(az[2], hB.x, wzz); fma2(az[3], hB.y, wzz);
            fma2(az[4], hC.x, wzz); fma2(az[5], hC.y, wzz);
            fma2(az[6], hD.x, wzz); fma2(az[7], hD.y, wzz);
            fma2(ar[0], hA.x, wrr); fma2(ar[1], hA.y, wrr);
            fma2(ar[2], hB.x, wrr); fma2(ar[3], hB.y, wrr);
            fma2(ar[4], hC.x, wrr); fma2(ar[5], hC.y, wrr);
            fma2(ar[6], hD.x, wrr); fma2(ar[7], hD.y, wrr);
        }
        // export partials for partner's rows (pairs ep0..ep0+4)
        {
            ulonglong2* pd = (ulonglong2*)(pexu + j * PEXSTR + (1 - kh) * 8);
            pd[0] = make_ulonglong2(az[ep0],     az[ep0 + 1]);
            pd[1] = make_ulonglong2(az[ep0 + 2], az[ep0 + 3]);
            pd[2] = make_ulonglong2(ar[ep0],     ar[ep0 + 1]);
            pd[3] = make_ulonglong2(ar[ep0 + 2], ar[ep0 + 3]);
        }
        __syncthreads();

        float zv[8];
        {
            const ulonglong2* ps = (const ulonglong2*)(pexu + j * PEXSTR + kh * 8);
            ulonglong2 z01 = ps[0], z23 = ps[1], r01 = ps[2], r23 = ps[3];
            add2(az[op0], z01.x);     add2(az[op0 + 1], z01.y);
            add2(az[op0 + 2], z23.x); add2(az[op0 + 3], z23.y);
            add2(ar[op0], r01.x);     add2(ar[op0 + 1], r01.y);
            add2(ar[op0 + 2], r23.x); add2(ar[op0 + 3], r23.y);
#pragma unroll
            for (int i = 0; i < 4; i++) {
                float2 z2 = unpack2(az[op0 + i]);
                float2 r2 = unpack2(ar[op0 + i]);
                zv[2 * i]     = sigmoidf_fast(z2.x);
                zv[2 * i + 1] = sigmoidf_fast(z2.y);
                float h0 = hsb[j * HSTR + orow + 2 * i];
                float h1 = hsb[j * HSTR + orow + 2 * i + 1];
                rhb[j * HSTR + orow + 2 * i]     = sigmoidf_fast(r2.x) * h0;
                rhb[j * HSTR + orow + 2 * i + 1] = sigmoidf_fast(r2.y) * h1;
            }
        }
        __syncthreads();   // rh complete + pex reads done

        // ---- stage 2: candidate partials over own k-half ----
        ull ah[8];
#pragma unroll
        for (int p = 0; p < 8; p++) {
            bool exp_p = (p >= ep0) && (p < ep0 + 4);
            if (exp_p) {
                float a0 = bh_j, a1 = bh_j;
#pragma unroll
                for (int v = 0; v < NVk; v++) {
                    a0 = fmaf(xs[2 * p][v], whx[v], a0);
                    a1 = fmaf(xs[2 * p + 1][v], whx[v], a1);
                }
                ah[p] = pack2(a0, a1);
            } else ah[p] = 0ULL;
        }
#pragma unroll 8
        for (int kk = 0; kk < 128; kk++) {
            int k = k0 + kk;
            float ws = ph[k * Hk];
            ull whh = pack2(ws, ws);
            const ulonglong2* rp = (const ulonglong2*)(rhb + k * HSTR);
            ulonglong2 rA = rp[0], rB = rp[1], rC = rp[2], rD = rp[3];
            fma2(ah[0], rA.x, whh); fma2(ah[1], rA.y, whh);
            fma2(ah[2], rB.x, whh); fma2(ah[3], rB.y, whh);
            fma2(ah[4], rC.x, whh); fma2(ah[5], rC.y, whh);
            fma2(ah[6], rD.x, whh); fma2(ah[7], rD.y, whh);
        }
        {
            ulonglong2* pd = (ulonglong2*)(pexu + j * PEXSTR + (1 - kh) * 8);
            pd[0] = make_ulonglong2(ah[ep0],     ah[ep0 + 1]);
            pd[1] = make_ulonglong2(ah[ep0 + 2], ah[ep0 + 3]);
        }
        __syncthreads();

        // ---- combine + epilogue for own 8 rows ----
        {
            const ulonglong2* ps = (const ulonglong2*)(pexu + j * PEXSTR + kh * 8);
            ulonglong2 h01 = ps[0], h23 = ps[1];
            add2(ah[op0], h01.x);     add2(ah[op0 + 1], h01.y);
            add2(ah[op0 + 2], h23.x); add2(ah[op0 + 3], h23.y);
#pragma unroll
            for (int i = 0; i < 4; i++) {
                float2 h2 = unpack2(ah[op0 + i]);
#pragma unroll
                for (int q = 0; q < 2; q++) {
                    int   lr   = 2 * i + q;
                    float pre  = tanhf(q ? h2.y : h2.x);
                    float hold = hsb[j * HSTR + orow + lr];
                    float hn   = (1.0f - zv[lr]) * hold + zv[lr] * pre;
                    int   len  = slen[orow + lr];
                    bool  valid = (t < len);

                    int base = (row0 + orow + lr) * (Tk * OW) + t * OW;
                    out_all[base + j]      = valid ? hn : 0.0f;
                    out_all[base + Hk + j] = valid ? lat[lr] : 0.0f;

                    if (valid) seg[lr] = fmaxf(seg[lr], hn);
                    if (t == len - 1) out_newh[(row0 + orow + lr) * Hk + j] = hn;

                    hsb[j * HSTR + orow + lr] = hn;
                }
            }
        }
    }

#pragma unroll
    for (int r = 0; r < 8; r++)
        out_seg[(row0 + orow + r) * Hk + j] = seg[r];
}

extern "C" void kernel_launch(void* const* d_in, const int* in_sizes, int n_in,
                              void* d_out, int out_size) {
    const float* x_seq   = (const float*)d_in[0];
    const float* hidden  = (const float*)d_in[1];
    const float* tree    = (const float*)d_in[2];
    const float* graph   = (const float*)d_in[3];
    const int*   lengths = (const int*)  d_in[4];
    const float* Wcs = (const float*)d_in[5];
    const float* bcs = (const float*)d_in[6];
    const float* Wz  = (const float*)d_in[7];
    const float* bz  = (const float*)d_in[8];
    const float* Wr  = (const float*)d_in[9];
    const float* br  = (const float*)d_in[10];
    const float* Wh  = (const float*)d_in[11];
    const float* bh  = (const float*)d_in[12];
    float* out = (float*)d_out;

    cudaFuncSetAttribute(gru_decoder_kernel,
                         cudaFuncAttributeMaxDynamicSharedMemorySize,
                         SMEM_F * (int)sizeof(float));
    repack_kernel<<<Hk * Hk / 256, 256>>>(Wz, Wr);
    gru_decoder_kernel<<<Bk / Rk, 512, SMEM_F * sizeof(float)>>>(
        x_seq, hidden, tree, graph, lengths,
        Wcs, bcs, Wz, bz, Wr, br, Wh, bh, out);
}